// round 11
// baseline (speedup 1.0000x reference)
#include <cuda_runtime.h>
#include <cstdint>

// out[tok, :] = sum_{l=0..7} weight[l, x[tok, l], :]
//   x:      16384 tokens x 8 int32 indices
//   weight: (8, 1024, 1024) f32, 32 MB (L2-resident)
//   out:    16384 x 1024 f32
//
// 2 consecutive tokens serialized per 256-thread CTA, both index vectors
// loaded up front; token B's gather issues while token A's reduce retires,
// overlapping load/reduce phases inside a single warp.

static constexpr int NTOK = 8 * 2048;   // 16384
static constexpr int K    = 1024;
static constexpr int D4   = 1024 / 4;   // 256 float4 per row

__device__ __forceinline__ float4 ldg_evict_last(const float4* p)
{
    float4 v;
    asm volatile("ld.global.nc.L1::evict_last.v4.f32 {%0, %1, %2, %3}, [%4];"
                 : "=f"(v.x), "=f"(v.y), "=f"(v.z), "=f"(v.w)
                 : "l"(p));
    return v;
}

__global__ __launch_bounds__(256)
void multi_embed_kernel(const int4* __restrict__ x4,
                        const float4* __restrict__ w,
                        float4* __restrict__ out)
{
    const int tok0 = blockIdx.x * 2;
    const int tid  = threadIdx.x;
    const float4* wt = w + tid;

    // Indices for BOTH tokens up front (4 uniform 16B broadcast loads).
    const int4 iA0 = __ldg(x4 + tok0 * 2);
    const int4 iB0 = __ldg(x4 + tok0 * 2 + 1);
    const int4 iA1 = __ldg(x4 + tok0 * 2 + 2);
    const int4 iB1 = __ldg(x4 + tok0 * 2 + 3);

    // ---- Token A: 8 loads in flight ----
    float4 a0 = ldg_evict_last(wt + (size_t)(0 * K + iA0.x) * D4);
    float4 a1 = ldg_evict_last(wt + (size_t)(1 * K + iA0.y) * D4);
    float4 a2 = ldg_evict_last(wt + (size_t)(2 * K + iA0.z) * D4);
    float4 a3 = ldg_evict_last(wt + (size_t)(3 * K + iA0.w) * D4);
    float4 a4 = ldg_evict_last(wt + (size_t)(4 * K + iB0.x) * D4);
    float4 a5 = ldg_evict_last(wt + (size_t)(5 * K + iB0.y) * D4);
    float4 a6 = ldg_evict_last(wt + (size_t)(6 * K + iB0.z) * D4);
    float4 a7 = ldg_evict_last(wt + (size_t)(7 * K + iB0.w) * D4);

    // ---- Token A reduce; ptxas can interleave token B loads as A regs die ----
    float4 acc0;
    acc0.x = (a0.x + a1.x) + (a2.x + a3.x);
    acc0.y = (a0.y + a1.y) + (a2.y + a3.y);
    acc0.z = (a0.z + a1.z) + (a2.z + a3.z);
    acc0.w = (a0.w + a1.w) + (a2.w + a3.w);

    float4 b0 = ldg_evict_last(wt + (size_t)(0 * K + iA1.x) * D4);
    float4 b1 = ldg_evict_last(wt + (size_t)(1 * K + iA1.y) * D4);
    float4 b2 = ldg_evict_last(wt + (size_t)(2 * K + iA1.z) * D4);
    float4 b3 = ldg_evict_last(wt + (size_t)(3 * K + iA1.w) * D4);

    acc0.x += (a4.x + a5.x) + (a6.x + a7.x);
    acc0.y += (a4.y + a5.y) + (a6.y + a7.y);
    acc0.z += (a4.z + a5.z) + (a6.z + a7.z);
    acc0.w += (a4.w + a5.w) + (a6.w + a7.w);

    float4 b4 = ldg_evict_last(wt + (size_t)(4 * K + iB1.x) * D4);
    float4 b5 = ldg_evict_last(wt + (size_t)(5 * K + iB1.y) * D4);
    float4 b6 = ldg_evict_last(wt + (size_t)(6 * K + iB1.z) * D4);
    float4 b7 = ldg_evict_last(wt + (size_t)(7 * K + iB1.w) * D4);

    float4* dst = out + (size_t)tok0 * D4 + tid;
    asm volatile("st.global.cs.v4.f32 [%0], {%1, %2, %3, %4};"
                 :: "l"(dst), "f"(acc0.x), "f"(acc0.y), "f"(acc0.z), "f"(acc0.w)
                 : "memory");

    // ---- Token B reduce + store ----
    float4 acc1;
    acc1.x = (b0.x + b1.x) + (b2.x + b3.x);
    acc1.y = (b0.y + b1.y) + (b2.y + b3.y);
    acc1.z = (b0.z + b1.z) + (b2.z + b3.z);
    acc1.w = (b0.w + b1.w) + (b2.w + b3.w);
    acc1.x += (b4.x + b5.x) + (b6.x + b7.x);
    acc1.y += (b4.y + b5.y) + (b6.y + b7.y);
    acc1.z += (b4.z + b5.z) + (b6.z + b7.z);
    acc1.w += (b4.w + b5.w) + (b6.w + b7.w);

    asm volatile("st.global.cs.v4.f32 [%0], {%1, %2, %3, %4};"
                 :: "l"(dst + D4), "f"(acc1.x), "f"(acc1.y), "f"(acc1.z), "f"(acc1.w)
                 : "memory");
}

extern "C" void kernel_launch(void* const* d_in, const int* in_sizes, int n_in,
                              void* d_out, int out_size)
{
    const int4*   x = (const int4*)d_in[0];
    const float4* w = (const float4*)d_in[1];
    float4*       o = (float4*)d_out;

    multi_embed_kernel<<<NTOK / 2, 256>>>(x, w, o);
}

// round 12
// speedup vs baseline: 1.0597x; 1.0597x over previous
#include <cuda_runtime.h>
#include <cstdint>

// out[tok, :] = sum_{l=0..7} weight[l, x[tok, l], :]
//   x:      16384 tokens x 8 int32 indices
//   weight: (8, 1024, 1024) f32, 32 MB (L2-resident)
//   out:    16384 x 1024 f32
//
// FINAL (measured best, R6 = 31.2 us): one 256-thread CTA per token,
// regs=32 -> 8 CTAs/SM; indices via two uniform 16B broadcast loads;
// 8 independent LDG.128 front-batched (MLP=8) with L1 evict_last on the
// L2-resident weight table; output via evict-first streaming store.
// Eleven alternative schedules/paths (persistent grid, 2-token fusion,
// 2-token pipeline, 128/512-thread CTAs, TMA bulk L1-bypass, extra cache
// hints) all measured 31.4-37.6 us: this sits on the compulsory-traffic
// L1tex/L2 queueing floor (~576 MB/run at ~18.5 TB/s through L1).

static constexpr int NTOK = 8 * 2048;   // 16384
static constexpr int K    = 1024;
static constexpr int D4   = 1024 / 4;   // 256 float4 per row

__device__ __forceinline__ float4 ldg_evict_last(const float4* p)
{
    float4 v;
    asm volatile("ld.global.nc.L1::evict_last.v4.f32 {%0, %1, %2, %3}, [%4];"
                 : "=f"(v.x), "=f"(v.y), "=f"(v.z), "=f"(v.w)
                 : "l"(p));
    return v;
}

__global__ __launch_bounds__(256, 8)
void multi_embed_kernel(const int4* __restrict__ x4,
                        const float4* __restrict__ w,
                        float4* __restrict__ out)
{
    const int tok = blockIdx.x;
    const int tid = threadIdx.x;

    // All 8 indices via two uniform 16B loads (warp-broadcast).
    const int4 iA = __ldg(x4 + tok * 2);       // l = 0..3
    const int4 iB = __ldg(x4 + tok * 2 + 1);   // l = 4..7

    const float4* wt = w + tid;

    // 8 independent LDG.128 front-batched (MLP=8), evict_last in L1.
    float4 a0 = ldg_evict_last(wt + (size_t)(0 * K + iA.x) * D4);
    float4 a1 = ldg_evict_last(wt + (size_t)(1 * K + iA.y) * D4);
    float4 a2 = ldg_evict_last(wt + (size_t)(2 * K + iA.z) * D4);
    float4 a3 = ldg_evict_last(wt + (size_t)(3 * K + iA.w) * D4);
    float4 b0 = ldg_evict_last(wt + (size_t)(4 * K + iB.x) * D4);
    float4 b1 = ldg_evict_last(wt + (size_t)(5 * K + iB.y) * D4);
    float4 b2 = ldg_evict_last(wt + (size_t)(6 * K + iB.z) * D4);
    float4 b3 = ldg_evict_last(wt + (size_t)(7 * K + iB.w) * D4);

    float4 acc;
    acc.x = (a0.x + a1.x) + (a2.x + a3.x);
    acc.y = (a0.y + a1.y) + (a2.y + a3.y);
    acc.z = (a0.z + a1.z) + (a2.z + a3.z);
    acc.w = (a0.w + a1.w) + (a2.w + a3.w);

    acc.x += (b0.x + b1.x) + (b2.x + b3.x);
    acc.y += (b0.y + b1.y) + (b2.y + b3.y);
    acc.z += (b0.z + b1.z) + (b2.z + b3.z);
    acc.w += (b0.w + b1.w) + (b2.w + b3.w);

    // Streaming store: evict-first, don't displace weight lines.
    float4* dst = out + (size_t)tok * D4 + tid;
    asm volatile("st.global.cs.v4.f32 [%0], {%1, %2, %3, %4};"
                 :: "l"(dst), "f"(acc.x), "f"(acc.y), "f"(acc.z), "f"(acc.w)
                 : "memory");
}

extern "C" void kernel_launch(void* const* d_in, const int* in_sizes, int n_in,
                              void* d_out, int out_size)
{
    const int4*   x = (const int4*)d_in[0];
    const float4* w = (const float4*)d_in[1];
    float4*       o = (float4*)d_out;

    multi_embed_kernel<<<NTOK, 256>>>(x, w, o);
}